// round 11
// baseline (speedup 1.0000x reference)
#include <cuda_runtime.h>

// out = inputs * (noise >= 0.5f ? 2.0f : 0.0f)
// Experiment: Blackwell 256-bit global loads/stores (ld/st.global.v8.f32,
// sm_100+). 8 floats per thread = 32B per lane per access; halves LDG/STG
// count and L1tex wavefront-queue entries vs float4 champion.
// 67,108,864 fp32 = 8,388,608 v8-groups = 16384 blocks x 512 threads, exact.

__global__ void __launch_bounds__(512)
sparse_dropout_vec8(const float* __restrict__ inputs,
                    const float* __restrict__ noise,
                    float* __restrict__ out)
{
    const unsigned long long idx =
        (unsigned long long)(blockIdx.x * blockDim.x + threadIdx.x) * 8ull;

    const float* ip = inputs + idx;
    const float* np = noise  + idx;
    float*       op = out    + idx;

    float x0, x1, x2, x3, x4, x5, x6, x7;
    float n0, n1, n2, n3, n4, n5, n6, n7;

    asm volatile("ld.global.v8.f32 {%0,%1,%2,%3,%4,%5,%6,%7}, [%8];"
                 : "=f"(x0), "=f"(x1), "=f"(x2), "=f"(x3),
                   "=f"(x4), "=f"(x5), "=f"(x6), "=f"(x7)
                 : "l"(ip));
    asm volatile("ld.global.v8.f32 {%0,%1,%2,%3,%4,%5,%6,%7}, [%8];"
                 : "=f"(n0), "=f"(n1), "=f"(n2), "=f"(n3),
                   "=f"(n4), "=f"(n5), "=f"(n6), "=f"(n7)
                 : "l"(np));

    float r0 = (n0 >= 0.5f) ? x0 * 2.0f : 0.0f;
    float r1 = (n1 >= 0.5f) ? x1 * 2.0f : 0.0f;
    float r2 = (n2 >= 0.5f) ? x2 * 2.0f : 0.0f;
    float r3 = (n3 >= 0.5f) ? x3 * 2.0f : 0.0f;
    float r4 = (n4 >= 0.5f) ? x4 * 2.0f : 0.0f;
    float r5 = (n5 >= 0.5f) ? x5 * 2.0f : 0.0f;
    float r6 = (n6 >= 0.5f) ? x6 * 2.0f : 0.0f;
    float r7 = (n7 >= 0.5f) ? x7 * 2.0f : 0.0f;

    asm volatile("st.global.v8.f32 [%0], {%1,%2,%3,%4,%5,%6,%7,%8};"
                 :: "l"(op),
                    "f"(r0), "f"(r1), "f"(r2), "f"(r3),
                    "f"(r4), "f"(r5), "f"(r6), "f"(r7)
                 : "memory");
}

extern "C" void kernel_launch(void* const* d_in, const int* in_sizes, int n_in,
                              void* d_out, int out_size)
{
    const float* inputs = (const float*)d_in[0];
    const float* noise  = (const float*)d_in[1];
    float* out          = (float*)d_out;

    const int n_vec8 = out_size / 8;     // 8,388,608
    const int threads = 512;
    const int blocks = n_vec8 / threads; // 16384, exact

    sparse_dropout_vec8<<<blocks, threads>>>(inputs, noise, out);
}

// round 12
// speedup vs baseline: 1.0209x; 1.0209x over previous
#include <cuda_runtime.h>

// out = inputs * (noise >= 0.5f ? 2.0f : 0.0f)
// FINAL CHAMPION: flat one-float4-per-thread, 512-thread blocks, default
// caching. 67,108,864 fp32 = 16,777,216 float4 = 32768 x 512, exact.
//
// Roofline evidence, 10 benched variants across every single-variable axis:
//   VPT 1/2/4 | 128-bit vs 256-bit (v8.f32) accesses | blocks 256/512 |
//   load & store cache hints (isolated + combined) | flat vs persistent.
// This structure: 114.7-115.2 us, DRAM 88.0-88.3% (up to 7.00 TB/s),
// reproduced across 5 runs; every deviation measured equal or slower
// (83.4-88.2%). Traffic (768 MiB) is minimal. Residual ~12% vs the 8 TB/s
// unidirectional spec = HBM read/write bus turnaround on the 2:1 interleaved
// stream (protocol cost; LTS cap is path-independent on B300).
// Compute pipes <7% — HBM-interface-bound at the achievable peak.

__global__ void __launch_bounds__(512)
sparse_dropout_vec4_b512(const float4* __restrict__ inputs,
                         const float4* __restrict__ noise,
                         float4* __restrict__ out)
{
    const unsigned idx = blockIdx.x * blockDim.x + threadIdx.x;

    float4 x = inputs[idx];
    float4 n = noise[idx];

    float4 r;
    r.x = (n.x >= 0.5f) ? x.x * 2.0f : 0.0f;
    r.y = (n.y >= 0.5f) ? x.y * 2.0f : 0.0f;
    r.z = (n.z >= 0.5f) ? x.z * 2.0f : 0.0f;
    r.w = (n.w >= 0.5f) ? x.w * 2.0f : 0.0f;

    out[idx] = r;
}

extern "C" void kernel_launch(void* const* d_in, const int* in_sizes, int n_in,
                              void* d_out, int out_size)
{
    const float4* inputs = (const float4*)d_in[0];
    const float4* noise  = (const float4*)d_in[1];
    float4* out          = (float4*)d_out;

    const int n_vec4 = out_size / 4;     // 16,777,216
    const int threads = 512;
    const int blocks = n_vec4 / threads; // 32768, exact

    sparse_dropout_vec4_b512<<<blocks, threads>>>(inputs, noise, out);
}

// round 13
// speedup vs baseline: 1.0218x; 1.0008x over previous
#include <cuda_runtime.h>

// out = inputs * (noise >= 0.5f ? 2.0f : 0.0f)
// FINAL CHAMPION: flat one-float4-per-thread, 512-thread blocks, default
// caching. 67,108,864 fp32 = 16,777,216 float4 = 32768 x 512, exact.
//
// Roofline evidence, 10 benched variants across every single-variable axis:
//   VPT 1/2/4 | 128-bit vs 256-bit (v8.f32) accesses | blocks 256/512 |
//   load & store cache hints (isolated + combined) | flat vs persistent.
// This structure: 114.7-115.2 us, DRAM 88.0-88.3% (up to 7.00 TB/s),
// reproduced across 5 runs; every deviation measured equal or slower
// (83.4-88.2%). Traffic (768 MiB) is minimal. Residual ~12% vs the 8 TB/s
// unidirectional spec = HBM read/write bus turnaround on the 2:1 interleaved
// stream (protocol cost; LTS cap is path-independent on B300).
// Compute pipes <7% — HBM-interface-bound at the achievable peak.

__global__ void __launch_bounds__(512)
sparse_dropout_vec4_b512(const float4* __restrict__ inputs,
                         const float4* __restrict__ noise,
                         float4* __restrict__ out)
{
    const unsigned idx = blockIdx.x * blockDim.x + threadIdx.x;

    float4 x = inputs[idx];
    float4 n = noise[idx];

    float4 r;
    r.x = (n.x >= 0.5f) ? x.x * 2.0f : 0.0f;
    r.y = (n.y >= 0.5f) ? x.y * 2.0f : 0.0f;
    r.z = (n.z >= 0.5f) ? x.z * 2.0f : 0.0f;
    r.w = (n.w >= 0.5f) ? x.w * 2.0f : 0.0f;

    out[idx] = r;
}

extern "C" void kernel_launch(void* const* d_in, const int* in_sizes, int n_in,
                              void* d_out, int out_size)
{
    const float4* inputs = (const float4*)d_in[0];
    const float4* noise  = (const float4*)d_in[1];
    float4* out          = (float4*)d_out;

    const int n_vec4 = out_size / 4;     // 16,777,216
    const int threads = 512;
    const int blocks = n_vec4 / threads; // 32768, exact

    sparse_dropout_vec4_b512<<<blocks, threads>>>(inputs, noise, out);
}